// round 15
// baseline (speedup 1.0000x reference)
#include <cuda_runtime.h>
#include <cstdint>

// Problem constants: B=16, H=8, R=400, F=256, dilated 2^k = 8
#define BH    128
#define RDIM  400
#define FDIM  256
#define NROWS (BH * RDIM)   // 51200
#define HALF_ROWS (NROWS / 2)

// Scratch: agg (tf32-rounded fp32 bits) [NROWS, FDIM] = 52.4 MB, W tf32 copy
__device__ float g_agg[(size_t)NROWS * FDIM];
__device__ float g_Wt[FDIM * FDIM];

// ---------------------------------------------------------------------------
// helpers
// ---------------------------------------------------------------------------
__device__ __forceinline__ uint32_t smem_u32(const void* p) {
    uint32_t a;
    asm("{ .reg .u64 t; cvta.to.shared.u64 t, %1; cvt.u32.u64 %0, t; }"
        : "=r"(a) : "l"(p));
    return a;
}

__device__ __forceinline__ float f2tf32(float x) {
    uint32_t r;
    asm("cvt.rna.tf32.f32 %0, %1;" : "=r"(r) : "f"(x));
    return __uint_as_float(r);
}

__device__ __forceinline__ void ldsm_x4(uint32_t r[4], uint32_t addr) {
    asm volatile("ldmatrix.sync.aligned.m8n8.x4.shared.b16 {%0,%1,%2,%3}, [%4];"
                 : "=r"(r[0]), "=r"(r[1]), "=r"(r[2]), "=r"(r[3]) : "r"(addr));
}

__device__ __forceinline__ void mma_tf32(float c[4], const uint32_t a[4],
                                         const uint32_t b0, const uint32_t b1) {
    asm volatile(
        "mma.sync.aligned.m16n8k8.row.col.f32.tf32.tf32.f32 "
        "{%0,%1,%2,%3}, {%4,%5,%6,%7}, {%8,%9}, {%0,%1,%2,%3};"
        : "+f"(c[0]), "+f"(c[1]), "+f"(c[2]), "+f"(c[3])
        : "r"(a[0]), "r"(a[1]), "r"(a[2]), "r"(a[3]), "r"(b0), "r"(b1));
}

__device__ __forceinline__ void cp_async16(uint32_t saddr, const void* gaddr) {
    asm volatile("cp.async.cg.shared.global [%0], [%1], 16;"
                 :: "r"(saddr), "l"(gaddr));
}
#define CP_COMMIT() asm volatile("cp.async.commit_group;")
#define CP_WAIT(N)  asm volatile("cp.async.wait_group %0;" :: "n"(N))

// ---------------------------------------------------------------------------
// Kernel 1: mask + sparse gather (R14 logic + row_base offset).
// TWO rows per warp, no smem, no block barriers. Blocks >= mask_blocks do
// the W -> tf32 conversion (only present in the first half's launch).
// ---------------------------------------------------------------------------
__global__ __launch_bounds__(256) void mask_agg_kernel(
    const float* __restrict__ A,
    const float* __restrict__ feats,
    const float* __restrict__ W,
    float* __restrict__ Wt,
    float* __restrict__ agg,
    int row_base, int mask_blocks)
{
    if (blockIdx.x >= (unsigned)mask_blocks) {
        int i = (blockIdx.x - mask_blocks) * 256 + threadIdx.x;
        float4 w = reinterpret_cast<const float4*>(W)[i];
        w.x = f2tf32(w.x); w.y = f2tf32(w.y);
        w.z = f2tf32(w.z); w.w = f2tf32(w.w);
        reinterpret_cast<float4*>(Wt)[i] = w;
        return;
    }

    const int lid  = threadIdx.x & 31;
    const int wid  = threadIdx.x >> 5;
    const int row0 = row_base + blockIdx.x * 16 + wid * 2;

    const float* ar0 = A + (size_t)row0 * RDIM;
    const float* ar1 = ar0 + RDIM;
    const float4* a40 = reinterpret_cast<const float4*>(ar0);
    const float4* a41 = reinterpret_cast<const float4*>(ar1);

    float v[2][6];
    #pragma unroll
    for (int rr = 0; rr < 2; rr++) {
        const float* ar = rr ? ar1 : ar0;
        v[rr][0] = __ldg(ar + 0);
        v[rr][1] = __ldg(ar + 8);
        v[rr][2] = __ldg(ar + 9);
        v[rr][3] = __ldg(ar + 10);
        v[rr][4] = __ldg(ar + 11);
        v[rr][5] = __ldg(ar + 12);
    }

    int cnt[2][6];
    #pragma unroll
    for (int rr = 0; rr < 2; rr++)
        #pragma unroll
        for (int k = 0; k < 6; k++) cnt[rr][k] = 0;

    // iteration 0 (j = 4*lid < 128): full stable tie-break logic
    {
        const int j = lid * 4;
        float4 f0 = __ldg(a40 + lid);
        float4 f1 = __ldg(a41 + lid);
        #pragma unroll
        for (int rr = 0; rr < 2; rr++) {
            float4 f = rr ? f1 : f0;
            cnt[rr][0] += (f.x > v[rr][0]) + (f.y > v[rr][0])
                        + (f.z > v[rr][0]) + (f.w > v[rr][0]);
            #pragma unroll
            for (int k = 1; k < 6; k++) {
                const int thr = 7 + k;   // 8..12
                cnt[rr][k] +=
                      ((f.x > v[rr][k]) | ((f.x == v[rr][k]) & (j     < thr)))
                    + ((f.y > v[rr][k]) | ((f.y == v[rr][k]) & (j + 1 < thr)))
                    + ((f.z > v[rr][k]) | ((f.z == v[rr][k]) & (j + 2 < thr)))
                    + ((f.w > v[rr][k]) | ((f.w == v[rr][k]) & (j + 3 < thr)));
            }
        }
    }
    // remaining iterations: j >= 128 > 12 -> pure greater-than counts
    for (int q = lid + 32; q < RDIM / 4; q += 32) {
        float4 f0 = __ldg(a40 + q);
        float4 f1 = __ldg(a41 + q);
        #pragma unroll
        for (int rr = 0; rr < 2; rr++) {
            float4 f = rr ? f1 : f0;
            #pragma unroll
            for (int k = 0; k < 6; k++)
                cnt[rr][k] += (f.x > v[rr][k]) + (f.y > v[rr][k])
                            + (f.z > v[rr][k]) + (f.w > v[rr][k]);
        }
    }

    int   p[2][7];
    float val[2][7];
    int   n[2];
    #pragma unroll
    for (int rr = 0; rr < 2; rr++) {
        #pragma unroll
        for (int k = 0; k < 6; k++)
            p[rr][k] = (int)__reduce_add_sync(0xffffffffu, (unsigned)cnt[rr][k]);
        const int row = row0 + rr;
        const int i   = row - (row / RDIM) * RDIM;
        p[rr][6] = i;
        bool diag = (p[rr][0] == i) | (p[rr][1] == i) | (p[rr][2] == i)
                  | (p[rr][3] == i) | (p[rr][4] == i) | (p[rr][5] == i);
        n[rr] = diag ? 6 : 7;
        const float* ar = rr ? ar1 : ar0;
        #pragma unroll
        for (int m = 0; m < 7; m++) val[rr][m] = __ldg(ar + p[rr][m]);
    }

    float4 acc[2][2];
    #pragma unroll
    for (int rr = 0; rr < 2; rr++) {
        acc[rr][0] = make_float4(0.f, 0.f, 0.f, 0.f);
        acc[rr][1] = make_float4(0.f, 0.f, 0.f, 0.f);
    }

    #pragma unroll
    for (int m = 0; m < 7; m++) {
        #pragma unroll
        for (int rr = 0; rr < 2; rr++) {
            if (m < n[rr]) {
                const int row = row0 + rr;
                const int bh  = row / RDIM;
                const float4* fb = reinterpret_cast<const float4*>(
                    feats + (size_t)bh * RDIM * FDIM);
                const float w = val[rr][m];
                const float4* src = fb + (size_t)p[rr][m] * (FDIM / 4) + lid * 2;
                float4 f0 = __ldg(src);
                float4 f1 = __ldg(src + 1);
                acc[rr][0].x += w * f0.x; acc[rr][0].y += w * f0.y;
                acc[rr][0].z += w * f0.z; acc[rr][0].w += w * f0.w;
                acc[rr][1].x += w * f1.x; acc[rr][1].y += w * f1.y;
                acc[rr][1].z += w * f1.z; acc[rr][1].w += w * f1.w;
            }
        }
    }

    #pragma unroll
    for (int rr = 0; rr < 2; rr++) {
        float4 a0 = acc[rr][0], a1 = acc[rr][1];
        a0.x = f2tf32(a0.x); a0.y = f2tf32(a0.y);
        a0.z = f2tf32(a0.z); a0.w = f2tf32(a0.w);
        a1.x = f2tf32(a1.x); a1.y = f2tf32(a1.y);
        a1.z = f2tf32(a1.z); a1.w = f2tf32(a1.w);
        float4* ao = reinterpret_cast<float4*>(
            agg + (size_t)(row0 + rr) * FDIM) + lid * 2;
        ao[0] = a0;
        ao[1] = a1;
    }
}

// ---------------------------------------------------------------------------
// Kernel 2: out = relu(agg @ W^T + b) + feats via mma.sync tf32 (m16n8k8).
// Verbatim R14 (CTA 128x64, 2-stage, 3 CTAs/SM) + m_base offset.
// ---------------------------------------------------------------------------
#define MT 128
#define NT 64
#define BK 32
#define NCHUNK (FDIM / BK)      // 8
#define RS 36
#define STAGE_FLOATS ((MT + NT) * RS)       // 6912 floats
#define NSTAGE 2
#define SMEM_FLOATS  (NSTAGE * STAGE_FLOATS)  // 55296 B
#define EPS 68

extern __shared__ float sm_dyn[];

__global__ __launch_bounds__(256, 3) void gemm_tf32_kernel(
    const float* __restrict__ agg,
    const float* __restrict__ Wt,
    const float* __restrict__ bias,
    const float* __restrict__ feats,
    float* __restrict__ out,
    int m_base)
{
    const int t   = threadIdx.x;
    const int wid = t >> 5;
    const int lid = t & 31;
    const int m0  = m_base + blockIdx.y * MT;
    const int n0  = blockIdx.x * NT;
    const int wm  = wid & 3;
    const int wn  = wid >> 2;

    const uint32_t sb = smem_u32(sm_dyn);

    const uint32_t aAddrBase = sb +
        ((uint32_t)((wm * 32 + ((lid >> 3) & 1) * 8 + (lid & 7)) * RS
                    + (lid >> 4) * 4) << 2);
    const uint32_t bAddrBase = sb + (uint32_t)(MT * RS * 4) +
        ((uint32_t)((wn * 32 + (lid >> 4) * 8 + (lid & 7)) * RS
                    + ((lid >> 3) & 1) * 4) << 2);

    float acc[2][4][4];
    #pragma unroll
    for (int a = 0; a < 2; a++)
        #pragma unroll
        for (int j = 0; j < 4; j++)
            #pragma unroll
            for (int k = 0; k < 4; k++) acc[a][j][k] = 0.f;

    auto issue_chunk = [&](int c, int stage) {
        const uint32_t sbase = sb + (uint32_t)(stage * STAGE_FLOATS * 4);
        #pragma unroll
        for (int u = 0; u < 6; u++) {
            int idx = u * 256 + t;          // 0..1535
            uint32_t sd;
            const float* gs;
            if (idx < 1024) {
                int r = idx >> 3, c4 = idx & 7;
                sd = sbase + (uint32_t)((r * RS + c4 * 4) << 2);
                gs = agg + (size_t)(m0 + r) * FDIM + c * BK + c4 * 4;
            } else {
                int e = idx - 1024;
                int r = e >> 3, c4 = e & 7;
                sd = sbase + (uint32_t)(MT * RS * 4) + (uint32_t)((r * RS + c4 * 4) << 2);
                gs = Wt + (size_t)(n0 + r) * FDIM + c * BK + c4 * 4;
            }
            cp_async16(sd, gs);
        }
        CP_COMMIT();
    };

    issue_chunk(0, 0);

    #pragma unroll 1
    for (int c = 0; c < NCHUNK; c++) {
        const int stage = c & 1;
        if (c + 1 < NCHUNK) {
            issue_chunk(c + 1, (c + 1) & 1);
            CP_WAIT(1);
        } else {
            CP_WAIT(0);
        }
        __syncthreads();

        const uint32_t aS = aAddrBase + (uint32_t)(stage * STAGE_FLOATS * 4);
        const uint32_t bS = bAddrBase + (uint32_t)(stage * STAGE_FLOATS * 4);

        #pragma unroll
        for (int ks = 0; ks < 4; ks++) {
            uint32_t afr[2][4];
            #pragma unroll
            for (int tm = 0; tm < 2; tm++)
                ldsm_x4(afr[tm], aS + (uint32_t)((tm * 16 * RS + ks * 8) << 2));

            uint32_t bfr[2][4];
            #pragma unroll
            for (int jj = 0; jj < 2; jj++)
                ldsm_x4(bfr[jj], bS + (uint32_t)((jj * 16 * RS + ks * 8) << 2));

            #pragma unroll
            for (int tm = 0; tm < 2; tm++)
                #pragma unroll
                for (int j = 0; j < 4; j++)
                    mma_tf32(acc[tm][j], afr[tm], bfr[j >> 1][(j & 1) * 2],
                             bfr[j >> 1][(j & 1) * 2 + 1]);
        }
        __syncthreads();
    }

    // epilogue: stage accumulators to smem, then coalesced store
    {
        float* ep = sm_dyn;
        #pragma unroll
        for (int tm = 0; tm < 2; tm++) {
            int rbase = wm * 32 + tm * 16 + (lid >> 2);
            int cbase = wn * 32 + (lid & 3) * 2;
            #pragma unroll
            for (int j = 0; j < 4; j++) {
                float2 lo = make_float2(acc[tm][j][0], acc[tm][j][1]);
                float2 hi = make_float2(acc[tm][j][2], acc[tm][j][3]);
                *reinterpret_cast<float2*>(&ep[rbase * EPS + cbase + j * 8])       = lo;
                *reinterpret_cast<float2*>(&ep[(rbase + 8) * EPS + cbase + j * 8]) = hi;
            }
        }
        __syncthreads();

        const float4* f4 = reinterpret_cast<const float4*>(feats);
        float4* o4 = reinterpret_cast<float4*>(out);
        const float4* b4 = reinterpret_cast<const float4*>(bias);
        #pragma unroll
        for (int it = 0; it < 8; it++) {
            int lin = it * 256 + t;
            int r   = lin >> 4;
            int c4  = lin & 15;
            float4 v = *reinterpret_cast<const float4*>(&ep[r * EPS + c4 * 4]);
            float4 bb = __ldg(&b4[(n0 >> 2) + c4]);
            size_t gi = ((size_t)(m0 + r) * FDIM + n0) / 4 + c4;
            float4 ff = __ldg(&f4[gi]);
            v.x = fmaxf(v.x + bb.x, 0.f) + ff.x;
            v.y = fmaxf(v.y + bb.y, 0.f) + ff.y;
            v.z = fmaxf(v.z + bb.z, 0.f) + ff.z;
            v.w = fmaxf(v.w + bb.w, 0.f) + ff.w;
            o4[gi] = v;
        }
    }
}

// ---------------------------------------------------------------------------
// Launch: two row-halves with a forked stream so gemm(half0) overlaps
// mask(half1). Fork/join via events — graph-capturable.
//   stream0: mask0+Wconv -> mask1 -> gemm1 -> wait(evB)
//   s2:      wait(evA) -> gemm0
// ---------------------------------------------------------------------------
extern "C" void kernel_launch(void* const* d_in, const int* in_sizes, int n_in,
                              void* d_out, int out_size)
{
    const float* A     = (const float*)d_in[0];  // [16,8,400,400]
    const float* feats = (const float*)d_in[1];  // [16,8,400,256]
    const float* W     = (const float*)d_in[2];  // [256,256]
    const float* bias  = (const float*)d_in[3];  // [256]
    float* out = (float*)d_out;

    float* agg;  cudaGetSymbolAddress((void**)&agg, g_agg);
    float* Wt;   cudaGetSymbolAddress((void**)&Wt,  g_Wt);

    static cudaStream_t s2 = nullptr;
    static cudaEvent_t  evA = nullptr, evB = nullptr;
    if (!s2) {
        cudaStreamCreateWithFlags(&s2, cudaStreamNonBlocking);
        cudaEventCreateWithFlags(&evA, cudaEventDisableTiming);
        cudaEventCreateWithFlags(&evB, cudaEventDisableTiming);
        cudaFuncSetAttribute(gemm_tf32_kernel,
                             cudaFuncAttributeMaxDynamicSharedMemorySize,
                             SMEM_FLOATS * 4);
    }

    const int HMB = HALF_ROWS / 16;          // 1600 mask blocks per half
    dim3 ghalf(FDIM / NT, HALF_ROWS / MT);   // (4, 200)

    // half 0 masks (+ W conversion in 64 tail blocks) on stream 0
    mask_agg_kernel<<<HMB + 64, 256>>>(A, feats, W, Wt, agg, 0, HMB);
    cudaEventRecord(evA, 0);

    // gemm half 0 on side stream, after mask half 0
    cudaStreamWaitEvent(s2, evA, 0);
    gemm_tf32_kernel<<<ghalf, 256, SMEM_FLOATS * 4, s2>>>(
        agg, Wt, bias, feats, out, 0);
    cudaEventRecord(evB, s2);

    // half 1 masks + gemm on stream 0 (overlap with gemm half 0)
    mask_agg_kernel<<<HMB, 256>>>(A, feats, W, Wt, agg, HALF_ROWS, HMB);
    gemm_tf32_kernel<<<ghalf, 256, SMEM_FLOATS * 4>>>(
        agg, Wt, bias, feats, out, HALF_ROWS);

    // join side stream back into stream 0
    cudaStreamWaitEvent(0, evB, 0);
}